// round 2
// baseline (speedup 1.0000x reference)
#include <cuda_runtime.h>
#include <cuda_bf16.h>
#include <cstddef>

// Problem constants
#define B_   128
#define S_   256
#define H_   1024
#define IN_  64
#define SD_  2
#define KTOT 1090            // SD + IN + H
#define XSTRIDE 1104         // KTOT padded to /16, zero tail
#define NG   4096            // 4*H

// Output layout (flat concat of the 4 return values, fp32)
#define OUT_OUTPUTS 0                                   // (B,S,1026)
#define OUT_ZF      ((size_t)B_ * S_ * (SD_ + H_))      // 33,619,968
#define OUT_CZF     (OUT_ZF + (size_t)B_ * (SD_ + H_))  // +131,328
#define OUT_COEF    (OUT_CZF + (size_t)B_ * (SD_ + H_)) // +131,328

// Scratch (device globals: no allocation allowed in kernel_launch)
__device__ float g_Xbuf[B_ * XSTRIDE];    // [x(2) | u_t(64) | h(1024) | pad(14)]
__device__ float g_gates[B_ * NG];
__device__ float g_cstate[B_ * H_];

__device__ __forceinline__ float sigf(float x) { return 1.0f / (1.0f + expf(-x)); }

// ---------------------------------------------------------------------------
// Init: pack X for step 0, load c state
// ---------------------------------------------------------------------------
__global__ void init_kernel(const float* __restrict__ z0,
                            const float* __restrict__ c0,
                            const float* __restrict__ rnn_input) {
    int b = blockIdx.x;
    int tid = threadIdx.x;
    for (int k = tid; k < XSTRIDE; k += 256) {
        float v;
        if (k < SD_)            v = z0[b * (SD_ + H_) + k];
        else if (k < SD_ + IN_) v = rnn_input[((size_t)b * S_) * IN_ + (k - SD_)];
        else if (k < KTOT)      v = z0[b * (SD_ + H_) + SD_ + (k - (SD_ + IN_))];
        else                    v = 0.0f;
        g_Xbuf[b * XSTRIDE + k] = v;
    }
    for (int n = tid; n < H_; n += 256)
        g_cstate[b * H_ + n] = c0[b * (SD_ + H_) + SD_ + n];
}

// ---------------------------------------------------------------------------
// Gate GEMM: gates[b][n] = sum_k X[b][k] * WU_w[n][k] + WU_b[n]
// Block tile: BM=128 (all batch), BN=32, BK=16. 128 blocks x 256 threads.
// Thread tile 4x4.
// ---------------------------------------------------------------------------
#define BM 128
#define BN 32
#define BK 16

__global__ void __launch_bounds__(256, 2)
gates_gemm(const float* __restrict__ W, const float* __restrict__ Wb) {
    __shared__ float Xs[BK][BM + 4];
    __shared__ float Ws[BK][BN + 4];

    const int tid  = threadIdx.x;
    const int n0   = blockIdx.x * BN;
    const int row  = (tid & 31) * 4;   // M offset of this thread's 4 rows
    const int colg = (tid >> 5) * 4;   // N offset of this thread's 4 cols

    float acc[4][4];
#pragma unroll
    for (int i = 0; i < 4; i++)
#pragma unroll
        for (int j = 0; j < 4; j++) acc[i][j] = 0.0f;

    const int ml = tid >> 2;            // 0..63
    const int kc = (tid & 3) * 4;       // 0,4,8,12

    for (int k0 = 0; k0 < KTOT; k0 += BK) {
        // Load X tile (padded, always in-bounds vector loads)
        float4 v0 = *(const float4*)(g_Xbuf + (size_t)ml * XSTRIDE + k0 + kc);
        float4 v1 = *(const float4*)(g_Xbuf + (size_t)(ml + 64) * XSTRIDE + k0 + kc);
        Xs[kc + 0][ml] = v0.x; Xs[kc + 1][ml] = v0.y;
        Xs[kc + 2][ml] = v0.z; Xs[kc + 3][ml] = v0.w;
        Xs[kc + 0][ml + 64] = v1.x; Xs[kc + 1][ml + 64] = v1.y;
        Xs[kc + 2][ml + 64] = v1.z; Xs[kc + 3][ml + 64] = v1.w;

        // Load W tile (rows are 1090 floats -> not 16B aligned; scalar + guard)
        if (tid < 128) {
            int nloc = tid >> 2;                 // 0..31
            const float* wp = W + (size_t)(n0 + nloc) * KTOT + k0 + kc;
#pragma unroll
            for (int e = 0; e < 4; e++) {
                float wv = (k0 + kc + e < KTOT) ? wp[e] : 0.0f;
                Ws[kc + e][nloc] = wv;
            }
        }
        __syncthreads();

#pragma unroll
        for (int kk = 0; kk < BK; kk++) {
            float4 a = *(const float4*)&Xs[kk][row];
            float4 bb = *(const float4*)&Ws[kk][colg];
            acc[0][0] += a.x * bb.x; acc[0][1] += a.x * bb.y;
            acc[0][2] += a.x * bb.z; acc[0][3] += a.x * bb.w;
            acc[1][0] += a.y * bb.x; acc[1][1] += a.y * bb.y;
            acc[1][2] += a.y * bb.z; acc[1][3] += a.y * bb.w;
            acc[2][0] += a.z * bb.x; acc[2][1] += a.z * bb.y;
            acc[2][2] += a.z * bb.z; acc[2][3] += a.z * bb.w;
            acc[3][0] += a.w * bb.x; acc[3][1] += a.w * bb.y;
            acc[3][2] += a.w * bb.z; acc[3][3] += a.w * bb.w;
        }
        __syncthreads();
    }

#pragma unroll
    for (int i = 0; i < 4; i++) {
        int m = row + i;
#pragma unroll
        for (int j = 0; j < 4; j++) {
            int n = n0 + colg + j;
            g_gates[(size_t)m * NG + n] = acc[i][j] + Wb[n];
        }
    }
}

// ---------------------------------------------------------------------------
// Pointwise step: LSTM cell + tiny (2xH) projections + ODE mix + state update
// One block per batch element (128 blocks x 256 threads).
// ---------------------------------------------------------------------------
__global__ void __launch_bounds__(256)
step_pointwise(const float* __restrict__ Wa, const float* __restrict__ Wab,
               const float* __restrict__ Wx, const float* __restrict__ Wxb,
               const float* __restrict__ Amat, const float* __restrict__ tau,
               const float* __restrict__ rnn_input,
               float* __restrict__ out, int s) {
    const int b = blockIdx.x;
    const int tid = threadIdx.x;

    const float* gb = g_gates + (size_t)b * NG;
    float* outz = out + ((size_t)(b * S_ + s)) * (SD_ + H_);

    float wa0 = 0.f, wa1 = 0.f, wx0 = 0.f, wx1 = 0.f;

#pragma unroll
    for (int j = 0; j < 4; j++) {
        int n = tid + j * 256;
        float i_ = gb[n];
        float f_ = gb[H_ + n];
        float g_ = gb[2 * H_ + n];
        float o_ = gb[3 * H_ + n];
        float c  = g_cstate[b * H_ + n];
        float cn = sigf(f_) * c + sigf(i_) * tanhf(g_);
        float hn = sigf(o_) * tanhf(cn);
        g_cstate[b * H_ + n] = cn;
        g_Xbuf[b * XSTRIDE + SD_ + IN_ + n] = hn;
        outz[SD_ + n] = hn;
        wa0 += Wa[n] * hn;       wa1 += Wa[H_ + n] * hn;
        wx0 += Wx[n] * hn;       wx1 += Wx[H_ + n] * hn;
    }

    // Block reduction of the 4 dot products
    __shared__ float red[8][4];
    unsigned mask = 0xffffffffu;
#pragma unroll
    for (int off = 16; off > 0; off >>= 1) {
        wa0 += __shfl_down_sync(mask, wa0, off);
        wa1 += __shfl_down_sync(mask, wa1, off);
        wx0 += __shfl_down_sync(mask, wx0, off);
        wx1 += __shfl_down_sync(mask, wx1, off);
    }
    if ((tid & 31) == 0) {
        red[tid >> 5][0] = wa0; red[tid >> 5][1] = wa1;
        red[tid >> 5][2] = wx0; red[tid >> 5][3] = wx1;
    }
    __syncthreads();

    if (tid == 0) {
        float s0 = 0.f, s1 = 0.f, s2 = 0.f, s3 = 0.f;
#pragma unroll
        for (int w = 0; w < 8; w++) {
            s0 += red[w][0]; s1 += red[w][1]; s2 += red[w][2]; s3 += red[w][3];
        }
        float xp0 = g_Xbuf[b * XSTRIDE + 0];
        float xp1 = g_Xbuf[b * XSTRIDE + 1];
        float t   = tau[b * S_ + s];
        float xm0 = xp0 + t * (Amat[0] * xp0 + Amat[1] * xp1);
        float xm1 = xp1 + t * (Amat[2] * xp0 + Amat[3] * xp1);
        float a0  = sigf(s0 + Wab[0]);
        float a1  = sigf(s1 + Wab[1]);
        float xt0 = s2 + Wxb[0];
        float xt1 = s3 + Wxb[1];
        float xn0 = a0 * xm0 + (1.0f - a0) * xt0;
        float xn1 = a1 * xm1 + (1.0f - a1) * xt1;
        g_Xbuf[b * XSTRIDE + 0] = xn0;
        g_Xbuf[b * XSTRIDE + 1] = xn1;
        outz[0] = xn0;
        outz[1] = xn1;
        float* cf = out + OUT_COEF + ((size_t)(b * S_ + s)) * SD_;
        cf[0] = a0;
        cf[1] = a1;
    }

    // Stage next step's input u_{s+1}
    if (s + 1 < S_ && tid < IN_) {
        g_Xbuf[b * XSTRIDE + SD_ + tid] =
            rnn_input[((size_t)b * S_ + (s + 1)) * IN_ + tid];
    }
}

// ---------------------------------------------------------------------------
// Epilogue: write z_f and c_z_f
// ---------------------------------------------------------------------------
__global__ void epilogue_kernel(const float* __restrict__ c0,
                                float* __restrict__ out) {
    int b = blockIdx.x;
    int tid = threadIdx.x;
    float* zf  = out + OUT_ZF  + (size_t)b * (SD_ + H_);
    float* czf = out + OUT_CZF + (size_t)b * (SD_ + H_);
    for (int k = tid; k < SD_ + H_; k += 256) {
        float zv, cv;
        if (k < SD_) {
            zv = g_Xbuf[b * XSTRIDE + k];
            cv = c0[b * (SD_ + H_) + k];
        } else {
            zv = g_Xbuf[b * XSTRIDE + SD_ + IN_ + (k - SD_)];
            cv = g_cstate[b * H_ + (k - SD_)];
        }
        zf[k]  = zv;
        czf[k] = cv;
    }
}

// ---------------------------------------------------------------------------
extern "C" void kernel_launch(void* const* d_in, const int* in_sizes, int n_in,
                              void* d_out, int out_size) {
    const float* rnn_input = (const float*)d_in[0];
    const float* z0        = (const float*)d_in[1];
    const float* c0        = (const float*)d_in[2];
    const float* tau       = (const float*)d_in[3];
    const float* A         = (const float*)d_in[4];
    const float* WU_w      = (const float*)d_in[5];
    const float* WU_b      = (const float*)d_in[6];
    const float* Wa_w      = (const float*)d_in[7];
    const float* Wa_b      = (const float*)d_in[8];
    const float* Wx_w      = (const float*)d_in[9];
    const float* Wx_b      = (const float*)d_in[10];
    float* out = (float*)d_out;

    init_kernel<<<B_, 256>>>(z0, c0, rnn_input);
    for (int s = 0; s < S_; s++) {
        gates_gemm<<<NG / BN, 256>>>(WU_w, WU_b);
        step_pointwise<<<B_, 256>>>(Wa_w, Wa_b, Wx_w, Wx_b, A, tau, rnn_input,
                                    out, s);
    }
    epilogue_kernel<<<B_, 256>>>(c0, out);
}

// round 4
// speedup vs baseline: 2.9591x; 2.9591x over previous
#include <cuda_runtime.h>
#include <cuda_bf16.h>
#include <cstdint>
#include <cstddef>

// ---------------------------------------------------------------------------
// Problem constants
// ---------------------------------------------------------------------------
#define B_   128
#define S_   256
#define H_   1024
#define IN_  64
#define SD_  2
#define KTOT 1090
#define NKB  36              // K blocks of 32 (KPAD = 1152)
#define ZW   (SD_ + H_)      // 1026
#define NG   4096

#define OUT_ZF   ((size_t)B_ * S_ * ZW)
#define OUT_CZF  (OUT_ZF + (size_t)B_ * ZW)
#define OUT_COEF (OUT_CZF + (size_t)B_ * ZW)

// Blocked layouts: rows padded to 40 bf16 (80 B) for conflict-free LDS
#define ROWB 40
#define XBLK_BYTES  (128 * ROWB * 2)          // 10240 per K-block
#define WBLK_BYTES  (32 * ROWB * 2)           // 2560 per (ntile, kb)
#define STAGE_BYTES (2 * XBLK_BYTES + 2 * WBLK_BYTES)   // 25600
#define SMEM_DYN    (128 + 2 * STAGE_BYTES)             // 51328

// ---------------------------------------------------------------------------
// Device-global scratch
// ---------------------------------------------------------------------------
__device__ __align__(128) __nv_bfloat16 g_Xhi[(size_t)NKB * 128 * ROWB];
__device__ __align__(128) __nv_bfloat16 g_Xlo[(size_t)NKB * 128 * ROWB];
__device__ __align__(128) __nv_bfloat16 g_Whi[(size_t)128 * NKB * 32 * ROWB];
__device__ __align__(128) __nv_bfloat16 g_Wlo[(size_t)128 * NKB * 32 * ROWB];
__device__ float g_gates[(size_t)B_ * NG];
__device__ float g_cstate[B_ * H_];
__device__ float g_xstate[B_ * 2];

// ---------------------------------------------------------------------------
// Helpers
// ---------------------------------------------------------------------------
__device__ __forceinline__ float sigf(float x) { return 1.0f / (1.0f + expf(-x)); }

__device__ __forceinline__ void store_x_hilo(int m, int k, float v) {
    int kb = k >> 5, kk = k & 31;
    size_t idx = ((size_t)kb * 128 + m) * ROWB + kk;
    __nv_bfloat16 hi = __float2bfloat16_rn(v);
    float r = v - __bfloat162float(hi);
    g_Xhi[idx] = hi;
    g_Xlo[idx] = __float2bfloat16_rn(r);
}

__device__ __forceinline__ uint32_t smem_u32(const void* p) {
    uint32_t a;
    asm("{ .reg .u64 t; cvta.to.shared.u64 t, %1; cvt.u32.u64 %0, t; }" : "=r"(a) : "l"(p));
    return a;
}

#define MBINIT(a, c)  asm volatile("mbarrier.init.shared.b64 [%0], %1;" :: "r"(a), "r"(c) : "memory")
#define MBEXPECT(a,b) asm volatile("mbarrier.arrive.expect_tx.shared.b64 _, [%0], %1;" :: "r"(a), "r"(b) : "memory")
#define MBARRIVE(a)   asm volatile("mbarrier.arrive.shared.b64 _, [%0];" :: "r"(a) : "memory")

#define MBAR_WAIT(mbar, ph) do {                                             \
    uint32_t _m = (mbar); uint32_t _p = (ph); uint32_t _ok;                  \
    asm volatile("{\n\t.reg .pred p;\n\t"                                    \
        "mbarrier.try_wait.parity.acquire.cta.shared::cta.b64 p, [%1], %2;\n\t" \
        "selp.b32 %0, 1, 0, p;\n\t}" : "=r"(_ok) : "r"(_m), "r"(_p) : "memory"); \
    while (!_ok) {                                                           \
        asm volatile("{\n\t.reg .pred p;\n\t"                                \
            "mbarrier.try_wait.parity.acquire.cta.shared::cta.b64 p, [%1], %2, 0x989680;\n\t" \
            "selp.b32 %0, 1, 0, p;\n\t}" : "=r"(_ok) : "r"(_m), "r"(_p) : "memory"); \
    }                                                                        \
} while (0)

__device__ __forceinline__ void bulk_g2s(uint32_t dst, const void* src, uint32_t bytes, uint32_t mbar) {
    asm volatile("cp.async.bulk.shared::cluster.global.mbarrier::complete_tx::bytes [%0], [%1], %2, [%3];"
                 :: "r"(dst), "l"(src), "r"(bytes), "r"(mbar) : "memory");
}

#define MMA_BF16(acc, a, b)                                                  \
    asm volatile("mma.sync.aligned.m16n8k16.row.col.f32.bf16.bf16.f32 "      \
                 "{%0,%1,%2,%3},{%4,%5,%6,%7},{%8,%9},{%0,%1,%2,%3};"        \
                 : "+f"((acc)[0]), "+f"((acc)[1]), "+f"((acc)[2]), "+f"((acc)[3]) \
                 : "r"((a)[0]), "r"((a)[1]), "r"((a)[2]), "r"((a)[3]),       \
                   "r"((b)[0]), "r"((b)[1]))

// ---------------------------------------------------------------------------
// prep_w: W [4096][1090] fp32 -> blocked split-bf16 images
// grid (128 ntiles, 36 kb), 128 threads
// ---------------------------------------------------------------------------
__global__ void prep_w(const float* __restrict__ W) {
    int nt = blockIdx.x, kb = blockIdx.y;
    size_t base = ((size_t)(nt * NKB + kb)) * 32 * ROWB;
    for (int i = threadIdx.x; i < 32 * ROWB; i += 128) {
        int nloc = i / ROWB, kk = i % ROWB;
        int n = nt * 32 + nloc;
        int k = kb * 32 + kk;
        float v = (kk < 32 && k < KTOT) ? W[(size_t)n * KTOT + k] : 0.0f;
        __nv_bfloat16 hi = __float2bfloat16_rn(v);
        float r = v - __bfloat162float(hi);
        g_Whi[base + i] = hi;
        g_Wlo[base + i] = __float2bfloat16_rn(r);
    }
}

// ---------------------------------------------------------------------------
// init_pack: X image for step 0 (incl. pads), states
// grid B_, 128 threads
// ---------------------------------------------------------------------------
__global__ void init_pack(const float* __restrict__ z0, const float* __restrict__ c0,
                          const float* __restrict__ rnn_input) {
    int b = blockIdx.x;
    for (int i = threadIdx.x; i < NKB * ROWB; i += 128) {
        int kb = i / ROWB, kk = i % ROWB;
        int k = kb * 32 + kk;
        float v = 0.0f;
        if (kk < 32) {
            if (k < SD_)            v = z0[b * ZW + k];
            else if (k < SD_ + IN_) v = rnn_input[((size_t)b * S_) * IN_ + (k - SD_)];
            else if (k < KTOT)      v = z0[b * ZW + SD_ + (k - (SD_ + IN_))];
        }
        size_t idx = ((size_t)kb * 128 + b) * ROWB + kk;
        __nv_bfloat16 hi = __float2bfloat16_rn(v);
        float r = v - __bfloat162float(hi);
        g_Xhi[idx] = hi;
        g_Xlo[idx] = __float2bfloat16_rn(r);
    }
    for (int n = threadIdx.x; n < H_; n += 128)
        g_cstate[b * H_ + n] = c0[b * ZW + SD_ + n];
    if (threadIdx.x < 2) g_xstate[b * 2 + threadIdx.x] = z0[b * ZW + threadIdx.x];
}

// ---------------------------------------------------------------------------
// gates_hmma: C[128][4096] = Xsplit @ Wsplit^T via bf16 HMMA (3-term split)
// grid = 128 CTAs (32 gate-cols each), 128 threads (4 warps, 32x32 per warp)
// ---------------------------------------------------------------------------
__global__ void __launch_bounds__(128, 1)
gates_hmma(int nt_dummy) {
    extern __shared__ char dsm[];
    uint32_t ub = smem_u32(dsm);
    const int nt  = blockIdx.x;
    const int tid = threadIdx.x;
    const int wid = tid >> 5;
    const int lane = tid & 31;
    const int lr = lane >> 2, lc = lane & 3;
    const int wm = wid * 32;

    uint32_t mb_full[2]  = {ub + 0,  ub + 8};
    uint32_t mb_empty[2] = {ub + 16, ub + 24};
    char* tiles = dsm + 128;

    if (tid == 0) {
        MBINIT(mb_full[0], 1);  MBINIT(mb_full[1], 1);
        MBINIT(mb_empty[0], 128); MBINIT(mb_empty[1], 128);
        asm volatile("fence.proxy.async.shared::cta;" ::: "memory");
    }
    __syncthreads();

    // Prologue: issue kb = 0, 1
    if (tid == 0) {
#pragma unroll
        for (int kb = 0; kb < 2; kb++) {
            int st = kb;
            uint32_t sb = ub + 128 + st * STAGE_BYTES;
            MBEXPECT(mb_full[st], STAGE_BYTES);
            bulk_g2s(sb,                      (const char*)g_Xhi + (size_t)kb * XBLK_BYTES, XBLK_BYTES, mb_full[st]);
            bulk_g2s(sb + XBLK_BYTES,         (const char*)g_Xlo + (size_t)kb * XBLK_BYTES, XBLK_BYTES, mb_full[st]);
            size_t woff = (size_t)(nt * NKB + kb) * WBLK_BYTES;
            bulk_g2s(sb + 2 * XBLK_BYTES,               (const char*)g_Whi + woff, WBLK_BYTES, mb_full[st]);
            bulk_g2s(sb + 2 * XBLK_BYTES + WBLK_BYTES,  (const char*)g_Wlo + woff, WBLK_BYTES, mb_full[st]);
        }
    }

    float acc[2][4][4];
#pragma unroll
    for (int mi = 0; mi < 2; mi++)
#pragma unroll
        for (int ni = 0; ni < 4; ni++)
#pragma unroll
            for (int e = 0; e < 4; e++) acc[mi][ni][e] = 0.0f;

    int fph[2] = {0, 0}, eph[2] = {0, 0};

    for (int kb = 0; kb < NKB; kb++) {
        int st = kb & 1;
        char* sx_hi = tiles + st * STAGE_BYTES;
        char* sx_lo = sx_hi + XBLK_BYTES;
        char* sw_hi = sx_hi + 2 * XBLK_BYTES;
        char* sw_lo = sw_hi + WBLK_BYTES;

        MBAR_WAIT(mb_full[st], fph[st]); fph[st] ^= 1;

#pragma unroll
        for (int ks = 0; ks < 2; ks++) {
            uint32_t ahi[2][4], alo[2][4], bhi[4][2], blo[4][2];
#pragma unroll
            for (int mi = 0; mi < 2; mi++) {
                int o = (wm + mi * 16 + lr) * 80 + ks * 32 + lc * 4;
                ahi[mi][0] = *(const uint32_t*)(sx_hi + o);
                ahi[mi][1] = *(const uint32_t*)(sx_hi + o + 640);
                ahi[mi][2] = *(const uint32_t*)(sx_hi + o + 16);
                ahi[mi][3] = *(const uint32_t*)(sx_hi + o + 656);
                alo[mi][0] = *(const uint32_t*)(sx_lo + o);
                alo[mi][1] = *(const uint32_t*)(sx_lo + o + 640);
                alo[mi][2] = *(const uint32_t*)(sx_lo + o + 16);
                alo[mi][3] = *(const uint32_t*)(sx_lo + o + 656);
            }
#pragma unroll
            for (int ni = 0; ni < 4; ni++) {
                int o = (ni * 8 + lr) * 80 + ks * 32 + lc * 4;
                bhi[ni][0] = *(const uint32_t*)(sw_hi + o);
                bhi[ni][1] = *(const uint32_t*)(sw_hi + o + 16);
                blo[ni][0] = *(const uint32_t*)(sw_lo + o);
                blo[ni][1] = *(const uint32_t*)(sw_lo + o + 16);
            }
#pragma unroll
            for (int mi = 0; mi < 2; mi++)
#pragma unroll
                for (int ni = 0; ni < 4; ni++) {
                    MMA_BF16(acc[mi][ni], ahi[mi], bhi[ni]);
                    MMA_BF16(acc[mi][ni], ahi[mi], blo[ni]);
                    MMA_BF16(acc[mi][ni], alo[mi], bhi[ni]);
                }
        }

        MBARRIVE(mb_empty[st]);

        if (tid == 0 && kb + 2 < NKB) {
            MBAR_WAIT(mb_empty[st], eph[st]); eph[st] ^= 1;
            int kn = kb + 2;
            uint32_t sb = ub + 128 + st * STAGE_BYTES;
            MBEXPECT(mb_full[st], STAGE_BYTES);
            bulk_g2s(sb,                      (const char*)g_Xhi + (size_t)kn * XBLK_BYTES, XBLK_BYTES, mb_full[st]);
            bulk_g2s(sb + XBLK_BYTES,         (const char*)g_Xlo + (size_t)kn * XBLK_BYTES, XBLK_BYTES, mb_full[st]);
            size_t woff = (size_t)(nt * NKB + kn) * WBLK_BYTES;
            bulk_g2s(sb + 2 * XBLK_BYTES,               (const char*)g_Whi + woff, WBLK_BYTES, mb_full[st]);
            bulk_g2s(sb + 2 * XBLK_BYTES + WBLK_BYTES,  (const char*)g_Wlo + woff, WBLK_BYTES, mb_full[st]);
        }
    }

    // Store accumulators
    const int n0 = nt * 32;
#pragma unroll
    for (int mi = 0; mi < 2; mi++) {
        int r0 = wm + mi * 16 + lr;
#pragma unroll
        for (int ni = 0; ni < 4; ni++) {
            int col = n0 + ni * 8 + lc * 2;
            g_gates[(size_t)r0 * NG + col]           = acc[mi][ni][0];
            g_gates[(size_t)r0 * NG + col + 1]       = acc[mi][ni][1];
            g_gates[(size_t)(r0 + 8) * NG + col]     = acc[mi][ni][2];
            g_gates[(size_t)(r0 + 8) * NG + col + 1] = acc[mi][ni][3];
        }
    }
}

// ---------------------------------------------------------------------------
// Pointwise step (proven in R2): LSTM cell + Wa/Wx dots + ODE mix + staging
// grid = B_, 256 threads
// ---------------------------------------------------------------------------
__global__ void __launch_bounds__(256)
step_pointwise(const float* __restrict__ WUb,
               const float* __restrict__ Wa, const float* __restrict__ Wab,
               const float* __restrict__ Wx, const float* __restrict__ Wxb,
               const float* __restrict__ Amat, const float* __restrict__ tau,
               const float* __restrict__ rnn_input,
               float* __restrict__ out, int s) {
    const int b = blockIdx.x;
    const int tid = threadIdx.x;

    const float* gb = g_gates + (size_t)b * NG;
    float* outz = out + ((size_t)b * S_ + s) * ZW;

    float wa0 = 0.f, wa1 = 0.f, wx0 = 0.f, wx1 = 0.f;

#pragma unroll
    for (int j = 0; j < 4; j++) {
        int n = tid + j * 256;
        float i_ = gb[n]          + WUb[n];
        float f_ = gb[H_ + n]     + WUb[H_ + n];
        float g_ = gb[2 * H_ + n] + WUb[2 * H_ + n];
        float o_ = gb[3 * H_ + n] + WUb[3 * H_ + n];
        float c  = g_cstate[b * H_ + n];
        float cn = sigf(f_) * c + sigf(i_) * tanhf(g_);
        float hn = sigf(o_) * tanhf(cn);
        g_cstate[b * H_ + n] = cn;
        store_x_hilo(b, SD_ + IN_ + n, hn);
        outz[SD_ + n] = hn;
        wa0 += Wa[n] * hn;       wa1 += Wa[H_ + n] * hn;
        wx0 += Wx[n] * hn;       wx1 += Wx[H_ + n] * hn;
    }

    __shared__ float red[8][4];
    unsigned mask = 0xffffffffu;
#pragma unroll
    for (int off = 16; off > 0; off >>= 1) {
        wa0 += __shfl_down_sync(mask, wa0, off);
        wa1 += __shfl_down_sync(mask, wa1, off);
        wx0 += __shfl_down_sync(mask, wx0, off);
        wx1 += __shfl_down_sync(mask, wx1, off);
    }
    if ((tid & 31) == 0) {
        red[tid >> 5][0] = wa0; red[tid >> 5][1] = wa1;
        red[tid >> 5][2] = wx0; red[tid >> 5][3] = wx1;
    }
    __syncthreads();

    if (tid == 0) {
        float s0 = 0.f, s1 = 0.f, s2 = 0.f, s3 = 0.f;
#pragma unroll
        for (int w = 0; w < 8; w++) {
            s0 += red[w][0]; s1 += red[w][1]; s2 += red[w][2]; s3 += red[w][3];
        }
        float xp0 = g_xstate[b * 2 + 0];
        float xp1 = g_xstate[b * 2 + 1];
        float t   = tau[b * S_ + s];
        float xm0 = xp0 + t * (Amat[0] * xp0 + Amat[1] * xp1);
        float xm1 = xp1 + t * (Amat[2] * xp0 + Amat[3] * xp1);
        float a0  = sigf(s0 + Wab[0]);
        float a1  = sigf(s1 + Wab[1]);
        float xt0 = s2 + Wxb[0];
        float xt1 = s3 + Wxb[1];
        float xn0 = a0 * xm0 + (1.0f - a0) * xt0;
        float xn1 = a1 * xm1 + (1.0f - a1) * xt1;
        g_xstate[b * 2 + 0] = xn0;
        g_xstate[b * 2 + 1] = xn1;
        store_x_hilo(b, 0, xn0);
        store_x_hilo(b, 1, xn1);
        outz[0] = xn0;
        outz[1] = xn1;
        float* cf = out + OUT_COEF + ((size_t)b * S_ + s) * SD_;
        cf[0] = a0;
        cf[1] = a1;
    }

    if (s + 1 < S_ && tid < IN_) {
        store_x_hilo(b, SD_ + tid,
                     rnn_input[((size_t)b * S_ + (s + 1)) * IN_ + tid]);
    }
}

// ---------------------------------------------------------------------------
// Final: z_f = outputs[:, -1, :], c_z_f = [c0[:, :2], c_final]
// ---------------------------------------------------------------------------
__global__ void final_out(const float* __restrict__ c0, float* __restrict__ out) {
    int b = blockIdx.x;
    float* zf  = out + OUT_ZF  + (size_t)b * ZW;
    float* czf = out + OUT_CZF + (size_t)b * ZW;
    const float* last = out + ((size_t)b * S_ + (S_ - 1)) * ZW;
    for (int k = threadIdx.x; k < ZW; k += 256) {
        zf[k] = last[k];
        czf[k] = (k < SD_) ? c0[b * ZW + k] : g_cstate[b * H_ + (k - SD_)];
    }
}

// ---------------------------------------------------------------------------
extern "C" void kernel_launch(void* const* d_in, const int* in_sizes, int n_in,
                              void* d_out, int out_size) {
    const float* rnn_input = (const float*)d_in[0];
    const float* z0        = (const float*)d_in[1];
    const float* c0        = (const float*)d_in[2];
    const float* tau       = (const float*)d_in[3];
    const float* A         = (const float*)d_in[4];
    const float* WU_w      = (const float*)d_in[5];
    const float* WU_b      = (const float*)d_in[6];
    const float* Wa_w      = (const float*)d_in[7];
    const float* Wa_b      = (const float*)d_in[8];
    const float* Wx_w      = (const float*)d_in[9];
    const float* Wx_b      = (const float*)d_in[10];
    float* out = (float*)d_out;

    cudaFuncSetAttribute(gates_hmma, cudaFuncAttributeMaxDynamicSharedMemorySize, SMEM_DYN);

    prep_w<<<dim3(128, NKB), 128>>>(WU_w);
    init_pack<<<B_, 128>>>(z0, c0, rnn_input);
    for (int s = 0; s < S_; s++) {
        gates_hmma<<<128, 128, SMEM_DYN>>>(0);
        step_pointwise<<<B_, 256>>>(WU_b, Wa_w, Wa_b, Wx_w, Wx_b, A, tau,
                                    rnn_input, out, s);
    }
    final_out<<<B_, 256>>>(c0, out);
}